// round 16
// baseline (speedup 1.0000x reference)
#include <cuda_runtime.h>
#include <cuda_fp16.h>
#include <cstdint>

// NonLocalLoss: B=4, C=64, N=4096, two branches sharing weights.
// out[b,c] = mean_n x + (fsg_w @ q)/N + fsg_b ; q[c] = (sum_n g[c,n]*E_n)/Z
// E_n = sum_m 2^(F'_nm), F' = (log2e*s)^T f  (flat softmax, shift-invariant).
// F' via single-product fp16 mma.sync; qdot fused into attn epilogue.

#define N_SP 4096
#define N_C  64
#define N_BB 8

__device__ __half g_s_h[(size_t)N_BB * N_SP * N_C];       // s [n][c] fp16
// f fused fragment layout: per row n, 128 B; group (kb,t) at (kb*4+t)*8
__device__ uint8_t g_f_fused[(size_t)N_BB * N_SP * 128];
__device__ __half g_g_h[(size_t)N_BB * N_C * N_SP];       // g fp16 [C][N]
__device__ float g_P_part[N_BB * 16 * N_C];               // per-(bb,rowtile,c)
__device__ float g_Z_part[N_BB * 16];                     // per-(bb,rowtile)
__device__ float g_sumx_part[N_BB * 32 * N_C];            // per-(bb,ntile,c)

#define STAGE_ROWB 132
#define PREP_SMEM  (82688 + 128 * STAGE_ROWB + 64)

#define FMA2(c, a, b) asm("fma.rn.f32x2 %0, %1, %2, %0;" : "+l"(c) : "l"(a), "l"(b))
__device__ __forceinline__ unsigned long long pack2(float lo, float hi) {
    unsigned long long p;
    asm("mov.b64 %0, {%1, %2};" : "=l"(p) : "f"(lo), "f"(hi));
    return p;
}
__device__ __forceinline__ void unpack2(unsigned long long p, float& lo, float& hi) {
    asm("mov.b64 {%0, %1}, %2;" : "=f"(lo), "=f"(hi) : "l"(p));
}

// ---------------------------------------------------------------------------
// prep: s,f,g = conv1x1(x) with packed FFMA2 core; fused sumx partials.
// ---------------------------------------------------------------------------
__global__ __launch_bounds__(256) void prep_kernel(
    const float* __restrict__ student, const float* __restrict__ teacher,
    const float* __restrict__ si_w, const float* __restrict__ si_b,
    const float* __restrict__ fi_w, const float* __restrict__ fi_b,
    const float* __restrict__ gi_w, const float* __restrict__ gi_b)
{
    extern __shared__ float sm[];
    float* sX = sm;                    // [64][128]
    float* sW = sm + 8192;             // [3][64][64]
    float* sB = sm + 8192 + 12288;     // [3][64]
    uint8_t* sStage = (uint8_t*)(sm + 8192 + 12288 + 192);   // 128 x 132 B
    const int tid = threadIdx.x;
    const int ntile = blockIdx.x, bb = blockIdx.y;
    const float* x = (bb < 4 ? student : teacher) + (size_t)(bb & 3) * N_C * N_SP;
    const int nbase = ntile * 128;
    const float LOG2E = 1.4426950408889634f;

    for (int i = tid; i < 8192; i += 256) {
        int c = i >> 7, j = i & 127;
        sX[i] = x[(size_t)c * N_SP + nbase + j];
    }
    for (int i = tid; i < 4096; i += 256) {
        sW[i]        = si_w[i] * LOG2E;
        sW[4096 + i] = fi_w[i];
        sW[8192 + i] = gi_w[i];
    }
    if (tid < 64) {
        sB[tid]       = si_b[tid] * LOG2E;
        sB[64 + tid]  = fi_b[tid];
        sB[128 + tid] = gi_b[tid];
    }
    __syncthreads();

    // fused sumx partials
    {
        const int c = tid >> 2, seg = tid & 3;
        const float* row = sX + c * 128 + seg * 32;
        float s = 0.f;
        #pragma unroll 8
        for (int i = 0; i < 32; ++i) s += row[i];
        s += __shfl_xor_sync(0xffffffffu, s, 1);
        s += __shfl_xor_sync(0xffffffffu, s, 2);
        if (seg == 0) g_sumx_part[(bb * 32 + ntile) * N_C + c] = s;
    }

    const int d0 = (tid >> 4) * 4, n0v = (tid & 15) * 4;
    #pragma unroll
    for (int mat = 0; mat < 3; ++mat) {
        const float* W = sW + mat * 4096;
        unsigned long long acc2[4][4];
        #pragma unroll
        for (int i = 0; i < 4; ++i)
            #pragma unroll
            for (int jp = 0; jp < 4; ++jp) acc2[i][jp] = 0ull;

        #pragma unroll 4
        for (int k4 = 0; k4 < 16; ++k4) {
            float4 wv[4];
            #pragma unroll
            for (int i = 0; i < 4; ++i)
                wv[i] = *(const float4*)&W[(d0 + i) * 64 + k4 * 4];
            #pragma unroll
            for (int kk = 0; kk < 4; ++kk) {
                const int k = k4 * 4 + kk;
                ulonglong2 xA = *(const ulonglong2*)&sX[k * 128 + n0v];
                ulonglong2 xB = *(const ulonglong2*)&sX[k * 128 + n0v + 64];
                #pragma unroll
                for (int i = 0; i < 4; ++i) {
                    const float wvi = ((const float*)&wv[i])[kk];
                    unsigned long long w2 = pack2(wvi, wvi);
                    FMA2(acc2[i][0], w2, xA.x);
                    FMA2(acc2[i][1], w2, xA.y);
                    FMA2(acc2[i][2], w2, xB.x);
                    FMA2(acc2[i][3], w2, xB.y);
                }
            }
        }
        float acc[4][8];
        #pragma unroll
        for (int i = 0; i < 4; ++i)
            #pragma unroll
            for (int jp = 0; jp < 4; ++jp)
                unpack2(acc2[i][jp], acc[i][2 * jp], acc[i][2 * jp + 1]);

        if (mat < 2) {
            #pragma unroll
            for (int j = 0; j < 8; ++j) {
                int row = n0v + (j < 4 ? j : 60 + j);
                __half h0 = __float2half_rn(acc[0][j] + sB[mat * 64 + d0 + 0]);
                __half h1 = __float2half_rn(acc[1][j] + sB[mat * 64 + d0 + 1]);
                __half h2 = __float2half_rn(acc[2][j] + sB[mat * 64 + d0 + 2]);
                __half h3 = __float2half_rn(acc[3][j] + sB[mat * 64 + d0 + 3]);
                unsigned p01 = (unsigned)__half_as_ushort(h0) | ((unsigned)__half_as_ushort(h1) << 16);
                unsigned p23 = (unsigned)__half_as_ushort(h2) | ((unsigned)__half_as_ushort(h3) << 16);
                if (mat == 0) {
                    *(unsigned*)(sStage + row * STAGE_ROWB + d0 * 2)     = p01;
                    *(unsigned*)(sStage + row * STAGE_ROWB + d0 * 2 + 4) = p23;
                } else {
                    const int kb  = d0 >> 4;
                    const int w0  = d0 & 15;
                    const int tt0 = (w0 & 7) >> 1;
                    const int hi4 = (w0 & 8) ? 4 : 0;
                    *(unsigned*)(sStage + row * STAGE_ROWB + (kb * 4 + tt0) * 8 + hi4)     = p01;
                    *(unsigned*)(sStage + row * STAGE_ROWB + (kb * 4 + tt0 + 1) * 8 + hi4) = p23;
                }
            }
            __syncthreads();
            {
                uint8_t* dst = (mat == 0)
                    ? (uint8_t*)(g_s_h + (size_t)bb * N_SP * N_C) + (size_t)nbase * 128
                    : g_f_fused + (size_t)bb * N_SP * 128 + (size_t)nbase * 128;
                #pragma unroll
                for (int pass = 0; pass < 16; ++pass) {
                    int m = pass * 1024 + tid * 4;
                    int row = m >> 7, off = m & 127;
                    unsigned v = *(const unsigned*)(sStage + row * STAGE_ROWB + off);
                    *(unsigned*)(dst + (size_t)row * 128 + off) = v;
                }
            }
            __syncthreads();
        } else {
            __half* out = g_g_h + (size_t)bb * N_C * N_SP;
            #pragma unroll
            for (int i = 0; i < 4; ++i) {
                float bias = sB[128 + d0 + i];
                __half a0 = __float2half_rn(acc[i][0] + bias);
                __half a1 = __float2half_rn(acc[i][1] + bias);
                __half a2 = __float2half_rn(acc[i][2] + bias);
                __half a3 = __float2half_rn(acc[i][3] + bias);
                __half b0 = __float2half_rn(acc[i][4] + bias);
                __half b1 = __float2half_rn(acc[i][5] + bias);
                __half b2 = __float2half_rn(acc[i][6] + bias);
                __half b3 = __float2half_rn(acc[i][7] + bias);
                unsigned pa0 = (unsigned)__half_as_ushort(a0) | ((unsigned)__half_as_ushort(a1) << 16);
                unsigned pa1 = (unsigned)__half_as_ushort(a2) | ((unsigned)__half_as_ushort(a3) << 16);
                unsigned pb0 = (unsigned)__half_as_ushort(b0) | ((unsigned)__half_as_ushort(b1) << 16);
                unsigned pb1 = (unsigned)__half_as_ushort(b2) | ((unsigned)__half_as_ushort(b3) << 16);
                *(uint2*)&out[(size_t)(d0 + i) * N_SP + nbase + n0v]      = make_uint2(pa0, pa1);
                *(uint2*)&out[(size_t)(d0 + i) * N_SP + nbase + n0v + 64] = make_uint2(pb0, pb1);
            }
        }
    }
}

// ---------------------------------------------------------------------------
// attn helpers
// ---------------------------------------------------------------------------
__device__ __forceinline__ uint32_t smem_u32(const void* p) {
    uint32_t a;
    asm("{ .reg .u64 t; cvta.to.shared.u64 t, %1; cvt.u32.u64 %0, t; }" : "=r"(a) : "l"(p));
    return a;
}
__device__ __forceinline__ void cp_async16s(uint32_t dst, const void* src) {
    asm volatile("cp.async.cg.shared.global [%0], [%1], 16;" :: "r"(dst), "l"(src) : "memory");
}
__device__ __forceinline__ float ex2f(float x) {
    float r; asm("ex2.approx.ftz.f32 %0, %1;" : "=f"(r) : "f"(x)); return r;
}
#define MMAF16(c, a, b0, b1) \
    asm volatile("mma.sync.aligned.m16n8k16.row.col.f32.f16.f16.f32 " \
        "{%0,%1,%2,%3}, {%4,%5,%6,%7}, {%8,%9}, {%0,%1,%2,%3};" \
        : "+f"((c)[0]), "+f"((c)[1]), "+f"((c)[2]), "+f"((c)[3]) \
        : "r"((a)[0]), "r"((a)[1]), "r"((a)[2]), "r"((a)[3]), "r"(b0), "r"(b1))

#define B_ROWSTR 160
#define B_BUF    (128 * B_ROWSTR)          // 20480 B
#define B_NBUF   3

// ---------------------------------------------------------------------------
// attn: mainloop unchanged (R13-validated); epilogue computes per-tile
// P_c = sum_n g[c,n]*E_n and Z = sum_n E_n (qdot fused, no g_rowE).
// grid (16 rowtiles, 8 bb) = 128 CTAs, 256 thr, smem 61440B.
// ---------------------------------------------------------------------------
__global__ __launch_bounds__(256, 1) void attn_kernel()
{
    extern __shared__ char rawsm[];
    const uint32_t base = smem_u32(rawsm);
    const int tid = threadIdx.x;
    const int wid = tid >> 5, lane = tid & 31;
    const int g = lane >> 2, t = lane & 3;
    const int rowtile = blockIdx.x, bb = blockIdx.y;
    const int rbase = rowtile * 256;
    const __half* SH = g_s_h + (size_t)bb * N_SP * N_C;
    const uint8_t* FF = g_f_fused + (size_t)bb * N_SP * 128;

    uint32_t aH[2][4][4];
    {
        const int r0 = rbase + 32 * wid + g;
        #pragma unroll
        for (int rb = 0; rb < 2; ++rb) {
            const int ra = r0 + 16 * rb, rbot = ra + 8;
            #pragma unroll
            for (int kb = 0; kb < 4; ++kb) {
                const int k0 = 16 * kb + 2 * t;
                aH[rb][kb][0] = *(const uint32_t*)&SH[(size_t)ra * N_C + k0];
                aH[rb][kb][1] = *(const uint32_t*)&SH[(size_t)rbot * N_C + k0];
                aH[rb][kb][2] = *(const uint32_t*)&SH[(size_t)ra * N_C + k0 + 8];
                aH[rb][kb][3] = *(const uint32_t*)&SH[(size_t)rbot * N_C + k0 + 8];
            }
        }
    }

    #pragma unroll
    for (int p = 0; p < 2; ++p) {
        #pragma unroll
        for (int i = 0; i < 4; ++i) {
            int ci = tid + i * 256;
            int row = ci >> 3, ch = ci & 7;
            cp_async16s(base + p * B_BUF + row * B_ROWSTR + ch * 16,
                        FF + (size_t)(p * 128 + row) * 128 + ch * 16);
        }
        asm volatile("cp.async.commit_group;" ::: "memory");
    }

    float e00 = 0.f, e01 = 0.f, e10 = 0.f, e11 = 0.f;
    int bufj = 0;
    for (int j = 0; j < 32; ++j) {
        asm volatile("cp.async.wait_group 1;" ::: "memory");
        __syncthreads();

        if (j + 2 < 32) {
            int buf2 = bufj + 2; if (buf2 >= 3) buf2 -= 3;
            const int cb = (j + 2) * 128;
            #pragma unroll
            for (int i = 0; i < 4; ++i) {
                int ci = tid + i * 256;
                int row = ci >> 3, ch = ci & 7;
                cp_async16s(base + buf2 * B_BUF + row * B_ROWSTR + ch * 16,
                            FF + (size_t)(cb + row) * 128 + ch * 16);
            }
            asm volatile("cp.async.commit_group;" ::: "memory");
        }

        const char* buf = rawsm + bufj * B_BUF;

        #pragma unroll 2
        for (int nt = 0; nt < 16; ++nt) {
            const char* rowp = buf + (nt * 8 + g) * B_ROWSTR + t * 8;
            uint2 bv[4];
            #pragma unroll
            for (int kb = 0; kb < 4; ++kb)
                bv[kb] = *(const uint2*)(rowp + kb * 32);

            float cA0[4] = {0.f,0.f,0.f,0.f};
            float cA1[4] = {0.f,0.f,0.f,0.f};
            #pragma unroll
            for (int kb = 0; kb < 4; ++kb) {
                MMAF16(cA0, aH[0][kb], bv[kb].x, bv[kb].y);
                MMAF16(cA1, aH[1][kb], bv[kb].x, bv[kb].y);
            }
            e00 += ex2f(cA0[0]) + ex2f(cA0[1]);
            e01 += ex2f(cA0[2]) + ex2f(cA0[3]);
            e10 += ex2f(cA1[0]) + ex2f(cA1[1]);
            e11 += ex2f(cA1[2]) + ex2f(cA1[3]);
        }

        if (++bufj == 3) bufj = 0;
    }

    #pragma unroll
    for (int off = 1; off < 4; off <<= 1) {
        e00 += __shfl_xor_sync(0xffffffffu, e00, off);
        e01 += __shfl_xor_sync(0xffffffffu, e01, off);
        e10 += __shfl_xor_sync(0xffffffffu, e10, off);
        e11 += __shfl_xor_sync(0xffffffffu, e11, off);
    }

    // ---- fused qdot epilogue (B buffers dead; reuse smem) ----
    float* sE = (float*)rawsm;         // 256 row-E values
    float* sP = sE + 256;              // 4x64 partials
    if (t == 0) {
        const int lr = 32 * wid + g;
        sE[lr]      = e00;
        sE[lr + 8]  = e01;
        sE[lr + 16] = e10;
        sE[lr + 24] = e11;
    }
    __syncthreads();

    {
        const int c = tid & 63, part = tid >> 6;
        const uint4* gp = (const uint4*)(g_g_h + ((size_t)bb * N_C + c) * N_SP + rbase + part * 64);
        const float* Ep = sE + part * 64;
        float p = 0.f;
        #pragma unroll
        for (int i = 0; i < 8; ++i) {
            uint4 gv = gp[i];
            float2 ga = __half22float2(*(const __half2*)&gv.x);
            float2 gb = __half22float2(*(const __half2*)&gv.y);
            float2 gc = __half22float2(*(const __half2*)&gv.z);
            float2 gd = __half22float2(*(const __half2*)&gv.w);
            p = fmaf(ga.x, Ep[8 * i + 0], p); p = fmaf(ga.y, Ep[8 * i + 1], p);
            p = fmaf(gb.x, Ep[8 * i + 2], p); p = fmaf(gb.y, Ep[8 * i + 3], p);
            p = fmaf(gc.x, Ep[8 * i + 4], p); p = fmaf(gc.y, Ep[8 * i + 5], p);
            p = fmaf(gd.x, Ep[8 * i + 6], p); p = fmaf(gd.y, Ep[8 * i + 7], p);
        }
        sP[part * 64 + c] = p;
    }
    __syncthreads();

    if (tid < 64) {
        float P = sP[tid] + sP[64 + tid] + sP[128 + tid] + sP[192 + tid];
        g_P_part[(bb * 16 + rowtile) * N_C + tid] = P;
    } else if (tid < 96) {
        const int l = tid - 64;
        float z = 0.f;
        #pragma unroll
        for (int k = 0; k < 8; ++k) z += sE[l + 32 * k];
        #pragma unroll
        for (int off = 16; off > 0; off >>= 1)
            z += __shfl_xor_sync(0xffffffffu, z, off);
        if (l == 0) g_Z_part[bb * 16 + rowtile] = z;
    }
}

// ---------------------------------------------------------------------------
// loss: fold P/Z/sumx partials via coalesced smem staging, q = P/Z, dots,
// MSE-sum, scale. One CTA, 256 threads, dynamic smem ~88 KB.
// ---------------------------------------------------------------------------
#define LOSS_SMEM ((16384 + 512 + 512 + 4160 + 256 + 128 + 8) * 4)

__global__ __launch_bounds__(256) void loss_kernel(const float* __restrict__ fsg_w,
                                                   const float* __restrict__ fsg_b,
                                                   float* __restrict__ out, int out_size)
{
    extern __shared__ float Ls[];
    float* sStage = Ls;                // 16384 (staging, reused)
    float* sQ  = Ls + 16384;           // 512
    float* sSX = sQ + 512;             // 512
    float* sWt = sSX + 512;            // 64*65
    float* red = sWt + 4160;           // 256
    float* sZp = red + 256;            // 128
    float* sZ  = sZp + 128;            // 8
    const int tid = threadIdx.x;

    // stage P_part (8192) + Z_part (128) + fsg_w transpose, all coalesced
    for (int i = tid; i < 8192; i += 256) sStage[i] = g_P_part[i];
    if (tid < 128) sZp[tid] = g_Z_part[tid];
    for (int i = tid; i < 4096; i += 256) {
        int d = i >> 6, c = i & 63;
        sWt[c * 65 + d] = fsg_w[i];
    }
    __syncthreads();

    if (tid < 8) {
        float z = 0.f;
        #pragma unroll
        for (int rt = 0; rt < 16; ++rt) z += sZp[tid * 16 + rt];
        sZ[tid] = z;
    }
    __syncthreads();

    for (int idx = tid; idx < 512; idx += 256) {
        int bb = idx >> 6, c = idx & 63;
        float P = 0.f;
        #pragma unroll
        for (int rt = 0; rt < 16; ++rt) P += sStage[bb * 1024 + rt * 64 + c];
        sQ[idx] = P / sZ[bb];
    }
    __syncthreads();                   // staging reads done

    // stage sumx_part (16384) and fold
    for (int i = tid; i < 16384; i += 256) sStage[i] = g_sumx_part[i];
    __syncthreads();
    for (int idx = tid; idx < 512; idx += 256) {
        int bb = idx >> 6, c = idx & 63;
        float s = 0.f;
        #pragma unroll
        for (int p = 0; p < 32; ++p) s += sStage[bb * 2048 + p * 64 + c];
        sSX[idx] = s;
    }
    __syncthreads();

    const int b = tid >> 6, d = tid & 63;
    float dot_s = 0.f, dot_t = 0.f;
    #pragma unroll 8
    for (int c = 0; c < 64; ++c) {
        float w = sWt[c * 65 + d];
        dot_s = fmaf(w, sQ[b * 64 + c], dot_s);
        dot_t = fmaf(w, sQ[(4 + b) * 64 + c], dot_t);
    }
    const float invN = 1.f / 4096.f;
    float out_s = sSX[b * 64 + d] * invN + dot_s * invN + fsg_b[d];
    float out_t = sSX[(4 + b) * 64 + d] * invN + dot_t * invN + fsg_b[d];
    float diff = out_s - out_t;
    red[tid] = diff * diff;
    __syncthreads();
    for (int off = 128; off > 0; off >>= 1) {
        if (tid < off) red[tid] += red[tid + off];
        __syncthreads();
    }
    const float nlB = 0.05f * 4e-4f * red[0];        // non_loss * B
    for (int i = tid; i < out_size; i += 256)
        out[i] = (i == 0) ? nlB : nlB * 0.25f;       // [non_loss*B, non_loss]
}

// ---------------------------------------------------------------------------
extern "C" void kernel_launch(void* const* d_in, const int* in_sizes, int n_in,
                              void* d_out, int out_size)
{
    (void)in_sizes; (void)n_in;
    const float* student = (const float*)d_in[0];
    const float* teacher = (const float*)d_in[1];
    const float* si_w  = (const float*)d_in[2];
    const float* si_b  = (const float*)d_in[3];
    const float* fi_w  = (const float*)d_in[4];
    const float* fi_b  = (const float*)d_in[5];
    const float* gi_w  = (const float*)d_in[6];
    const float* gi_b  = (const float*)d_in[7];
    const float* fsg_w = (const float*)d_in[8];
    const float* fsg_b = (const float*)d_in[9];

    cudaFuncSetAttribute(prep_kernel, cudaFuncAttributeMaxDynamicSharedMemorySize, PREP_SMEM);
    cudaFuncSetAttribute(attn_kernel, cudaFuncAttributeMaxDynamicSharedMemorySize, B_NBUF * B_BUF);
    cudaFuncSetAttribute(loss_kernel, cudaFuncAttributeMaxDynamicSharedMemorySize, LOSS_SMEM);

    prep_kernel<<<dim3(32, 8), 256, PREP_SMEM>>>(student, teacher, si_w, si_b, fi_w, fi_b, gi_w, gi_b);
    attn_kernel<<<dim3(16, 8), 256, B_NBUF * B_BUF>>>();
    loss_kernel<<<1, 256, LOSS_SMEM>>>(fsg_w, fsg_b, (float*)d_out, out_size);
}